// round 14
// baseline (speedup 1.0000x reference)
#include <cuda_runtime.h>

// Scaled dot-product attention, B=4 H=16 S=2048 D=64, fp32 in/out.
// R13: R12 structure at 4-warp CTA (64q x 64k tile), 3 CTAs/SM for occupancy.
//  - Q/K prepass permutes each 8-word d-group (slot = (t&3)*2 + (t>>2)) so
//    MMA fragment pairs load as LDS.64.
//  - V prepass transposes per head to Vt[d][k'] with the same within-8 perm.
//  - cp.async double-buffered K/V tiles, 2x-unrolled compile-time buffers.

#define DH 64
#define BM 64
#define BN 64
#define NT 128
#define SEQ 2048
#define NKT (SEQ / BN)     /* 32 */

#define KS_STRIDE 72       /* words per K row; 72 % 32 == 8 -> conflict-free LDS.64 */
#define VT_STRIDE 72       /* words per Vt row */
#define KS_BYTES (BN * KS_STRIDE * 4)       /* 18432 */
#define VT_BYTES (DH * VT_STRIDE * 4)       /* 18432 */
#define BUF_BYTES (KS_BYTES + VT_BYTES)     /* 36864 */
#define SMEM_BYTES (2 * BUF_BYTES)          /* 73728 -> 3 CTAs/SM */

#define TOT (4 * 16 * 2048 * 64)            /* 8388608 elements per tensor */

__device__ float g_Qc[TOT];   // permuted-d, scaled, tf32 bits
__device__ float g_Kc[TOT];   // permuted-d, tf32 bits
__device__ float g_Vt[TOT];   // per-head transposed [d][k'], permuted-k, tf32 bits

__device__ __forceinline__ unsigned tf32b(float x) {
    unsigned u;
    asm("cvt.rna.tf32.f32 %0, %1;" : "=r"(u) : "f"(x));
    return u;
}
__device__ __forceinline__ float ex2f(float x) {
    float r; asm("ex2.approx.f32 %0, %1;" : "=f"(r) : "f"(x)); return r;
}
__device__ __forceinline__ void mma_tf32(float c[4],
                                         const unsigned a[4],
                                         unsigned b0, unsigned b1) {
    asm("mma.sync.aligned.m16n8k8.row.col.f32.tf32.tf32.f32 "
        "{%0,%1,%2,%3}, {%4,%5,%6,%7}, {%8,%9}, {%0,%1,%2,%3};"
        : "+f"(c[0]), "+f"(c[1]), "+f"(c[2]), "+f"(c[3])
        : "r"(a[0]), "r"(a[1]), "r"(a[2]), "r"(a[3]), "r"(b0), "r"(b1));
}
__device__ __forceinline__ void cpa16(void* dst_smem, const void* src) {
    unsigned d = (unsigned)__cvta_generic_to_shared(dst_smem);
    asm volatile("cp.async.cg.shared.global [%0], [%1], 16;" :: "r"(d), "l"(src));
}
__device__ __forceinline__ void cpa_commit() {
    asm volatile("cp.async.commit_group;");
}
template <int N> __device__ __forceinline__ void cpa_wait() {
    asm volatile("cp.async.wait_group %0;" :: "n"(N));
}

// ---- prepass A: fp32 -> tf32 bits, permute each 8-word d-group ----
// out slots {0..7} = in t {0,4,1,5,2,6,3,7}
__global__ void __launch_bounds__(256) cvt_perm_kernel(
    const float* __restrict__ src, float* __restrict__ dst, float scale)
{
    int i = blockIdx.x * 256 + threadIdx.x;      // one 8-word group per thread
    const float4* s = (const float4*)(src) + 2 * i;
    float4 in0 = s[0];          // t = 0..3
    float4 in1 = s[1];          // t = 4..7
    uint4 o0, o1;
    o0.x = tf32b(in0.x * scale);  o0.y = tf32b(in1.x * scale);
    o0.z = tf32b(in0.y * scale);  o0.w = tf32b(in1.y * scale);
    o1.x = tf32b(in0.z * scale);  o1.y = tf32b(in1.z * scale);
    o1.z = tf32b(in0.w * scale);  o1.w = tf32b(in1.w * scale);
    uint4* d = (uint4*)(dst) + 2 * i;
    d[0] = o0;
    d[1] = o1;
}

// ---- prepass B: per-head transpose V[k][d] -> Vt[d][k'], k' perm within 8 ----
__global__ void __launch_bounds__(256) transpose_v_kernel(
    const float* __restrict__ V, float* __restrict__ Vt)
{
    __shared__ float t[32][33];
    const int k0 = blockIdx.x * 32;
    const int d0 = blockIdx.y * 32;
    const size_t hb = (size_t)blockIdx.z * (SEQ * DH);
    const int txi = threadIdx.x;   // 0..31
    const int tyi = threadIdx.y;   // 0..7

    #pragma unroll
    for (int j = 0; j < 4; ++j) {
        int k = k0 + tyi + j * 8;
        t[tyi + j * 8][txi] = V[hb + (size_t)k * DH + d0 + txi];
    }
    __syncthreads();
    const int kp = k0 + ((txi & ~7) | ((txi & 3) << 1) | ((txi & 7) >> 2));
    #pragma unroll
    for (int j = 0; j < 4; ++j) {
        int d = d0 + tyi + j * 8;
        unsigned u = tf32b(t[txi][tyi + j * 8]);
        Vt[hb + (size_t)d * SEQ + kp] = __uint_as_float(u);
    }
}

__device__ __forceinline__ void prefetch_tile(
    unsigned* __restrict__ Kn, unsigned* __restrict__ Vn,
    const float* __restrict__ Kc, const float* __restrict__ Vtc,
    int kb, int tid)
{
    #pragma unroll
    for (int it = 0; it < 8; ++it) {             // K: 64 rows x 64 words
        int idx = tid + it * NT;
        int row = idx >> 4;
        int d4 = (idx & 15) << 2;
        cpa16(&Kn[row * KS_STRIDE + d4], &Kc[(size_t)(kb + row) * DH + d4]);
    }
    #pragma unroll
    for (int it = 0; it < 8; ++it) {             // Vt: 64 d-rows x 64 k-words
        int idx = tid + it * NT;
        int row = idx >> 4;
        int c4 = (idx & 15) << 2;
        cpa16(&Vn[row * VT_STRIDE + c4], &Vtc[(size_t)row * SEQ + kb + c4]);
    }
    cpa_commit();
}

__device__ __forceinline__ void compute_tile(
    const unsigned* __restrict__ Kb, const unsigned* __restrict__ Vb,
    const unsigned (&qa)[8][4], float (&o)[8][4],
    float& m0, float& m1, float& l0, float& l1,
    int gid, int tig, int srcA, int srcB, bool odd)
{
    // ---- GEMM1: S = Q @ K^T (8 n-tiles of 16x8); B-frags are LDS.64 ----
    float c[8][4];
    #pragma unroll
    for (int nt = 0; nt < 8; ++nt)
        #pragma unroll
        for (int j = 0; j < 4; ++j) c[nt][j] = 0.0f;

    #pragma unroll
    for (int kc = 0; kc < 8; ++kc) {
        #pragma unroll
        for (int nt = 0; nt < 8; ++nt) {
            uint2 b = *(const uint2*)&Kb[(nt * 8 + gid) * KS_STRIDE + kc * 8 + 2 * tig];
            mma_tf32(c[nt], qa[kc], b.x, b.y);
        }
    }

    // ---- online softmax (log2 domain); rows gid, gid+8 ----
    float mx0 = -1e30f, mx1 = -1e30f;
    #pragma unroll
    for (int nt = 0; nt < 8; ++nt) {
        mx0 = fmaxf(mx0, fmaxf(c[nt][0], c[nt][1]));
        mx1 = fmaxf(mx1, fmaxf(c[nt][2], c[nt][3]));
    }
    #pragma unroll
    for (int off = 1; off <= 2; off <<= 1) {
        mx0 = fmaxf(mx0, __shfl_xor_sync(0xffffffffu, mx0, off));
        mx1 = fmaxf(mx1, __shfl_xor_sync(0xffffffffu, mx1, off));
    }
    float mn0 = fmaxf(m0, mx0), mn1 = fmaxf(m1, mx1);
    float f0 = ex2f(m0 - mn0), f1 = ex2f(m1 - mn1);
    m0 = mn0; m1 = mn1;

    float s0 = 0.0f, s1 = 0.0f;
    #pragma unroll
    for (int nt = 0; nt < 8; ++nt) {
        c[nt][0] = ex2f(c[nt][0] - mn0);
        c[nt][1] = ex2f(c[nt][1] - mn0);
        c[nt][2] = ex2f(c[nt][2] - mn1);
        c[nt][3] = ex2f(c[nt][3] - mn1);
        s0 += c[nt][0] + c[nt][1];
        s1 += c[nt][2] + c[nt][3];
    }
    #pragma unroll
    for (int off = 1; off <= 2; off <<= 1) {
        s0 += __shfl_xor_sync(0xffffffffu, s0, off);
        s1 += __shfl_xor_sync(0xffffffffu, s1, off);
    }
    l0 = l0 * f0 + s0;
    l1 = l1 * f1 + s1;

    #pragma unroll
    for (int nt = 0; nt < 8; ++nt) {
        o[nt][0] *= f0; o[nt][1] *= f0;
        o[nt][2] *= f1; o[nt][3] *= f1;
    }

    // ---- P: C-frag -> A-frag (quad shuffles), fused with GEMM2 ----
    #pragma unroll
    for (int kc = 0; kc < 8; ++kc) {
        float x0 = __shfl_sync(0xffffffffu, c[kc][0], srcA);
        float x1 = __shfl_sync(0xffffffffu, c[kc][1], srcA);
        float y0 = __shfl_sync(0xffffffffu, c[kc][0], srcB);
        float y1 = __shfl_sync(0xffffffffu, c[kc][1], srcB);
        float z0 = __shfl_sync(0xffffffffu, c[kc][2], srcA);
        float z1 = __shfl_sync(0xffffffffu, c[kc][3], srcA);
        float w0 = __shfl_sync(0xffffffffu, c[kc][2], srcB);
        float w1 = __shfl_sync(0xffffffffu, c[kc][3], srcB);
        unsigned pa[4];
        pa[0] = tf32b(odd ? x1 : x0);
        pa[2] = tf32b(odd ? y1 : y0);
        pa[1] = tf32b(odd ? z1 : z0);
        pa[3] = tf32b(odd ? w1 : w0);
        #pragma unroll
        for (int nt2 = 0; nt2 < 8; ++nt2) {
            uint2 b = *(const uint2*)&Vb[(nt2 * 8 + gid) * VT_STRIDE + kc * 8 + 2 * tig];
            mma_tf32(o[nt2], pa, b.x, b.y);
        }
    }
}

__global__ void __launch_bounds__(NT, 3) attn_tf32_v3_kernel(float* __restrict__ O)
{
    extern __shared__ char smem[];
    unsigned* Ks0 = (unsigned*)smem;
    unsigned* Vs0 = (unsigned*)(smem + KS_BYTES);
    unsigned* Ks1 = (unsigned*)(smem + BUF_BYTES);
    unsigned* Vs1 = (unsigned*)(smem + BUF_BYTES + KS_BYTES);

    const int tid  = threadIdx.x;
    const int lane = tid & 31;
    const int warp = tid >> 5;
    const int gid  = lane >> 2;
    const int tig  = lane & 3;

    const size_t base = (size_t)blockIdx.y * ((size_t)SEQ * DH);
    const int qbase = blockIdx.x * BM;

    const float* Kc  = g_Kc + base;
    const float* Vtc = g_Vt + base;

    // ---- prologue: async-stage Q (into Ks1 region) then tile 0 into buf0 ----
    {
        const float* Qc = g_Qc + base + (size_t)qbase * DH;
        #pragma unroll
        for (int it = 0; it < 8; ++it) {
            int idx = tid + it * NT;
            int row = idx >> 4;
            int d4 = (idx & 15) << 2;
            cpa16(&Ks1[row * KS_STRIDE + d4], &Qc[row * DH + d4]);
        }
        cpa_commit();
    }
    prefetch_tile(Ks0, Vs0, Kc, Vtc, 0, tid);

    cpa_wait<1>();          // Q ready (tile 0 may still fly)
    __syncthreads();

    unsigned qa[8][4];      // permuted layout: (a0,a2) and (a1,a3) adjacent
    {
        const int r0 = warp * 16 + gid;
        #pragma unroll
        for (int kc = 0; kc < 8; ++kc) {
            uint2 lo = *(const uint2*)&Ks1[(r0    ) * KS_STRIDE + kc * 8 + 2 * tig];
            uint2 hi = *(const uint2*)&Ks1[(r0 + 8) * KS_STRIDE + kc * 8 + 2 * tig];
            qa[kc][0] = lo.x;  qa[kc][2] = lo.y;
            qa[kc][1] = hi.x;  qa[kc][3] = hi.y;
        }
    }
    __syncthreads();        // Q-frag reads done before Ks1 is reused

    float o[8][4];
    #pragma unroll
    for (int nt = 0; nt < 8; ++nt)
        #pragma unroll
        for (int j = 0; j < 4; ++j) o[nt][j] = 0.0f;
    float m0 = -1e30f, m1 = -1e30f, l0 = 0.0f, l1 = 0.0f;

    const int srcA = (lane & 28) | (tig >> 1);
    const int srcB = srcA + 2;
    const bool odd = (tig & 1) != 0;

    #pragma unroll 1
    for (int kt2 = 0; kt2 < NKT / 2; ++kt2) {
        const int ktB = 2 * kt2 + 1;

        // ---- step A: prefetch tile ktB into buf1; compute buf0 ----
        prefetch_tile(Ks1, Vs1, Kc, Vtc, ktB * BN, tid);
        cpa_wait<1>();       // tile 2*kt2 complete
        __syncthreads();
        compute_tile(Ks0, Vs0, qa, o, m0, m1, l0, l1,
                     gid, tig, srcA, srcB, odd);
        __syncthreads();     // buf0 consumers done before next prefetch into it

        // ---- step B: prefetch tile ktB+1 into buf0; compute buf1 ----
        if (kt2 < NKT / 2 - 1) {
            prefetch_tile(Ks0, Vs0, Kc, Vtc, (ktB + 1) * BN, tid);
            cpa_wait<1>();   // tile ktB complete
        } else {
            cpa_wait<0>();   // last tile: drain everything
        }
        __syncthreads();
        compute_tile(Ks1, Vs1, qa, o, m0, m1, l0, l1,
                     gid, tig, srcA, srcB, odd);
        __syncthreads();     // buf1 consumers done before next prefetch into it
    }

    // ---- epilogue ----
    const float inv0 = 1.0f / l0, inv1 = 1.0f / l1;
    const int r0 = qbase + warp * 16 + gid;
    const int r1 = r0 + 8;
    #pragma unroll
    for (int nt2 = 0; nt2 < 8; ++nt2) {
        float2 e0, e1;
        e0.x = o[nt2][0] * inv0; e0.y = o[nt2][1] * inv0;
        e1.x = o[nt2][2] * inv1; e1.y = o[nt2][3] * inv1;
        *(float2*)&O[base + (size_t)r0 * DH + nt2 * 8 + 2 * tig] = e0;
        *(float2*)&O[base + (size_t)r1 * DH + nt2 * 8 + 2 * tig] = e1;
    }
}

extern "C" void kernel_launch(void* const* d_in, const int* in_sizes, int n_in,
                              void* d_out, int out_size)
{
    const float* Q = (const float*)d_in[0];
    const float* K = (const float*)d_in[1];
    const float* V = (const float*)d_in[2];
    float* O = (float*)d_out;

    const float SC = 0.125f * 1.4426950408889634f;

    float *dQc, *dKc, *dVt;
    cudaGetSymbolAddress((void**)&dQc, g_Qc);
    cudaGetSymbolAddress((void**)&dKc, g_Kc);
    cudaGetSymbolAddress((void**)&dVt, g_Vt);

    const int n8 = TOT / 8;
    cvt_perm_kernel<<<n8 / 256, 256>>>(Q, dQc, SC);
    cvt_perm_kernel<<<n8 / 256, 256>>>(K, dKc, 1.0f);

    dim3 tg(SEQ / 32, DH / 32, 64);
    transpose_v_kernel<<<tg, dim3(32, 8)>>>(V, dVt);

    cudaFuncSetAttribute(attn_tf32_v3_kernel,
                         cudaFuncAttributeMaxDynamicSharedMemorySize, SMEM_BYTES);

    dim3 grid(SEQ / BM, 64);
    attn_tf32_v3_kernel<<<grid, NT, SMEM_BYTES>>>(O);
}

// round 15
// speedup vs baseline: 2.3993x; 2.3993x over previous
#include <cuda_runtime.h>
#include <cuda_fp16.h>

// Scaled dot-product attention, B=4 H=16 S=2048 D=64, fp32 in/out.
// R14: R12 pipeline, fp16 m16n8k16 MMA (same 10-bit mantissa as tf32).
//  - Q/K prepass: fp32 -> fp16 pairs, pair-words permuted within each
//    8-word (16-element) group: slot = (j&3)*2 + (j>>2)  -> LDS.64 frags.
//  - V prepass: per-head transpose to Vt[d][k], same within-group pair perm.
//  - P transpose for GEMM2 is free: C-frag pairs pack directly into A-frags.
// cp.async double-buffered K/V tiles, 2x-unrolled compile-time buffers.

#define DH 64
#define BM 128
#define BN 128
#define NT 256
#define SEQ 2048
#define NKT (SEQ / BN)     /* 16 */

#define KS_STRIDE 40       /* words/row (32 data); 40/2 % 16 == 4 -> conflict-free */
#define VT_STRIDE 72       /* words/row (64 data); 72/2 % 16 == 4 */
#define KS_BYTES (BN * KS_STRIDE * 4)       /* 20480 */
#define VT_BYTES (DH * VT_STRIDE * 4)       /* 18432 */
#define BUF_BYTES (KS_BYTES + VT_BYTES)     /* 38912 */
#define SMEM_BYTES (2 * BUF_BYTES)          /* 77824 */

#define TOT (4 * 16 * 2048 * 64)            /* 8388608 elements per tensor */

__device__ unsigned g_Qh[TOT / 2];   // fp16 pairs, permuted-d, scaled
__device__ unsigned g_Kh[TOT / 2];   // fp16 pairs, permuted-d
__device__ unsigned g_Vh[TOT / 2];   // fp16 pairs, per-head transposed [d][k], permuted-k

__device__ __forceinline__ unsigned packh2(float hi, float lo) {
    unsigned u;
    asm("cvt.rn.f16x2.f32 %0, %1, %2;" : "=r"(u) : "f"(hi), "f"(lo));
    return u;
}
__device__ __forceinline__ float ex2f(float x) {
    float r; asm("ex2.approx.f32 %0, %1;" : "=f"(r) : "f"(x)); return r;
}
__device__ __forceinline__ void mma_f16(float c[4],
                                        unsigned a0, unsigned a1,
                                        unsigned a2, unsigned a3,
                                        unsigned b0, unsigned b1) {
    asm("mma.sync.aligned.m16n8k16.row.col.f32.f16.f16.f32 "
        "{%0,%1,%2,%3}, {%4,%5,%6,%7}, {%8,%9}, {%0,%1,%2,%3};"
        : "+f"(c[0]), "+f"(c[1]), "+f"(c[2]), "+f"(c[3])
        : "r"(a0), "r"(a1), "r"(a2), "r"(a3), "r"(b0), "r"(b1));
}
__device__ __forceinline__ void cpa16(void* dst_smem, const void* src) {
    unsigned d = (unsigned)__cvta_generic_to_shared(dst_smem);
    asm volatile("cp.async.cg.shared.global [%0], [%1], 16;" :: "r"(d), "l"(src));
}
__device__ __forceinline__ void cpa_commit() {
    asm volatile("cp.async.commit_group;");
}
template <int N> __device__ __forceinline__ void cpa_wait() {
    asm volatile("cp.async.wait_group %0;" :: "n"(N));
}

// ---- prepass A: fp32 -> fp16 pairs, permute pair-words within 16-elem group ----
// slot s holds pair j = (s&1)*4 + (s>>1); pair j = elements {2j, 2j+1} (lo=2j)
__global__ void __launch_bounds__(256) cvt_h2_kernel(
    const float* __restrict__ src, unsigned* __restrict__ dst, float scale)
{
    int i = blockIdx.x * 256 + threadIdx.x;      // one 16-element group per thread
    const float4* s = (const float4*)(src) + 4 * (size_t)i;
    float4 v0 = s[0], v1 = s[1], v2 = s[2], v3 = s[3];
    float f[16] = { v0.x, v0.y, v0.z, v0.w, v1.x, v1.y, v1.z, v1.w,
                    v2.x, v2.y, v2.z, v2.w, v3.x, v3.y, v3.z, v3.w };
    #pragma unroll
    for (int t = 0; t < 16; ++t) f[t] *= scale;
    uint4 oA, oB;
    oA.x = packh2(f[1],  f[0]);   // slot0 = pair0
    oA.y = packh2(f[9],  f[8]);   // slot1 = pair4
    oA.z = packh2(f[3],  f[2]);   // slot2 = pair1
    oA.w = packh2(f[11], f[10]);  // slot3 = pair5
    oB.x = packh2(f[5],  f[4]);   // slot4 = pair2
    oB.y = packh2(f[13], f[12]);  // slot5 = pair6
    oB.z = packh2(f[7],  f[6]);   // slot6 = pair3
    oB.w = packh2(f[15], f[14]);  // slot7 = pair7
    uint4* d = (uint4*)(dst) + 2 * (size_t)i;
    d[0] = oA;
    d[1] = oB;
}

// ---- prepass B: per-head transpose V[k][d] -> Vt[d][k], pair-permuted fp16 ----
__global__ void __launch_bounds__(256) transpose_vh_kernel(
    const float* __restrict__ V, unsigned* __restrict__ Vt)
{
    __shared__ float t[32][33];
    const int k0 = blockIdx.x * 32;
    const int d0 = blockIdx.y * 32;
    const size_t hb = (size_t)blockIdx.z * (SEQ * DH);
    const int txi = threadIdx.x;   // 0..31
    const int tyi = threadIdx.y;   // 0..7

    #pragma unroll
    for (int j = 0; j < 4; ++j) {
        int k = k0 + tyi + j * 8;
        t[tyi + j * 8][txi] = V[hb + (size_t)k * DH + d0 + txi];
    }
    __syncthreads();
    // thread writes 4 d-rows (txi selects d-col of tile -> a transposed row)
    #pragma unroll
    for (int j = 0; j < 4; ++j) {
        int dl = tyi + j * 8;                // local d in tile
        int d = d0 + dl;
        #pragma unroll
        for (int g = 0; g < 2; ++g) {        // two 16-k groups in the 32-k run
            const float* r = &t[g * 16][0];
            uint4 oA, oB;
            oA.x = packh2(r[1 * 33 + dl],  r[0 * 33 + dl]);
            oA.y = packh2(r[9 * 33 + dl],  r[8 * 33 + dl]);
            oA.z = packh2(r[3 * 33 + dl],  r[2 * 33 + dl]);
            oA.w = packh2(r[11 * 33 + dl], r[10 * 33 + dl]);
            oB.x = packh2(r[5 * 33 + dl],  r[4 * 33 + dl]);
            oB.y = packh2(r[13 * 33 + dl], r[12 * 33 + dl]);
            oB.z = packh2(r[7 * 33 + dl],  r[6 * 33 + dl]);
            oB.w = packh2(r[15 * 33 + dl], r[14 * 33 + dl]);
            size_t wbase = (hb >> 1) + (size_t)d * (SEQ / 2) + ((k0 >> 1) + g * 8);
            *(uint4*)&Vt[wbase]     = oA;
            *(uint4*)&Vt[wbase + 4] = oB;
        }
    }
}

__device__ __forceinline__ void prefetch_tile(
    unsigned* __restrict__ Kn, unsigned* __restrict__ Vn,
    const unsigned* __restrict__ Kc, const unsigned* __restrict__ Vtc,
    int kb, int tid)
{
    #pragma unroll
    for (int it = 0; it < 4; ++it) {             // K: 128 rows x 32 words (8 chunks)
        int idx = tid + it * NT;
        int row = idx >> 3;
        int c = (idx & 7) << 2;
        cpa16(&Kn[row * KS_STRIDE + c], &Kc[(size_t)(kb + row) * 32 + c]);
    }
    #pragma unroll
    for (int it = 0; it < 4; ++it) {             // Vt: 64 rows x 64 words (16 chunks)
        int idx = tid + it * NT;
        int row = idx >> 4;
        int c = (idx & 15) << 2;
        cpa16(&Vn[row * VT_STRIDE + c], &Vtc[(size_t)row * (SEQ / 2) + (kb >> 1) + c]);
    }
    cpa_commit();
}

__device__ __forceinline__ void compute_tile(
    const unsigned* __restrict__ Kb, const unsigned* __restrict__ Vb,
    const unsigned (&qa)[4][4], float (&o)[8][4],
    float& m0, float& m1, float& l0, float& l1,
    int gid, int tig)
{
    // ---- GEMM1: S = Q @ K^T (16 n-tiles of 16x8, 4 k16 chunks) ----
    float c[16][4];
    #pragma unroll
    for (int nt = 0; nt < 16; ++nt)
        #pragma unroll
        for (int j = 0; j < 4; ++j) c[nt][j] = 0.0f;

    #pragma unroll
    for (int kc = 0; kc < 4; ++kc) {
        #pragma unroll
        for (int nt = 0; nt < 16; ++nt) {
            uint2 b = *(const uint2*)&Kb[(nt * 8 + gid) * KS_STRIDE + kc * 8 + 2 * tig];
            mma_f16(c[nt], qa[kc][0], qa[kc][1], qa[kc][2], qa[kc][3], b.x, b.y);
        }
    }

    // ---- online softmax (log2 domain); rows gid, gid+8 ----
    float mx0 = -1e30f, mx1 = -1e30f;
    #pragma unroll
    for (int nt = 0; nt < 16; ++nt) {
        mx0 = fmaxf(mx0, fmaxf(c[nt][0], c[nt][1]));
        mx1 = fmaxf(mx1, fmaxf(c[nt][2], c[nt][3]));
    }
    #pragma unroll
    for (int off = 1; off <= 2; off <<= 1) {
        mx0 = fmaxf(mx0, __shfl_xor_sync(0xffffffffu, mx0, off));
        mx1 = fmaxf(mx1, __shfl_xor_sync(0xffffffffu, mx1, off));
    }
    float mn0 = fmaxf(m0, mx0), mn1 = fmaxf(m1, mx1);
    float f0 = ex2f(m0 - mn0), f1 = ex2f(m1 - mn1);
    m0 = mn0; m1 = mn1;

    float s0 = 0.0f, s1 = 0.0f;
    #pragma unroll
    for (int nt = 0; nt < 16; ++nt) {
        c[nt][0] = ex2f(c[nt][0] - mn0);
        c[nt][1] = ex2f(c[nt][1] - mn0);
        c[nt][2] = ex2f(c[nt][2] - mn1);
        c[nt][3] = ex2f(c[nt][3] - mn1);
        s0 += c[nt][0] + c[nt][1];
        s1 += c[nt][2] + c[nt][3];
    }
    #pragma unroll
    for (int off = 1; off <= 2; off <<= 1) {
        s0 += __shfl_xor_sync(0xffffffffu, s0, off);
        s1 += __shfl_xor_sync(0xffffffffu, s1, off);
    }
    l0 = l0 * f0 + s0;
    l1 = l1 * f1 + s1;

    #pragma unroll
    for (int nt = 0; nt < 8; ++nt) {
        o[nt][0] *= f0; o[nt][1] *= f0;
        o[nt][2] *= f1; o[nt][3] *= f1;
    }

    // ---- GEMM2: O += P @ V. FREE transpose: C-frag pairs -> A-frag. ----
    #pragma unroll
    for (int kc = 0; kc < 8; ++kc) {
        unsigned pa0 = packh2(c[2 * kc][1],     c[2 * kc][0]);
        unsigned pa1 = packh2(c[2 * kc][3],     c[2 * kc][2]);
        unsigned pa2 = packh2(c[2 * kc + 1][1], c[2 * kc + 1][0]);
        unsigned pa3 = packh2(c[2 * kc + 1][3], c[2 * kc + 1][2]);
        #pragma unroll
        for (int nt2 = 0; nt2 < 8; ++nt2) {
            uint2 b = *(const uint2*)&Vb[(nt2 * 8 + gid) * VT_STRIDE + kc * 8 + 2 * tig];
            mma_f16(o[nt2], pa0, pa1, pa2, pa3, b.x, b.y);
        }
    }
}

__global__ void __launch_bounds__(NT, 1) attn_f16_kernel(float* __restrict__ O)
{
    extern __shared__ char smem[];
    unsigned* Ks0 = (unsigned*)smem;
    unsigned* Vs0 = (unsigned*)(smem + KS_BYTES);
    unsigned* Ks1 = (unsigned*)(smem + BUF_BYTES);
    unsigned* Vs1 = (unsigned*)(smem + BUF_BYTES + KS_BYTES);

    const int tid  = threadIdx.x;
    const int lane = tid & 31;
    const int warp = tid >> 5;
    const int gid  = lane >> 2;
    const int tig  = lane & 3;

    const size_t base = (size_t)blockIdx.y * ((size_t)SEQ * DH);
    const int qbase = blockIdx.x * BM;

    const unsigned* Kc  = g_Kh + (base >> 1);
    const unsigned* Vtc = g_Vh + (base >> 1);

    // ---- prologue: async-stage Q (into Ks1 region) then tile 0 into buf0 ----
    {
        const unsigned* Qc = g_Qh + (base >> 1) + (size_t)qbase * 32;
        #pragma unroll
        for (int it = 0; it < 4; ++it) {
            int idx = tid + it * NT;
            int row = idx >> 3;
            int c = (idx & 7) << 2;
            cpa16(&Ks1[row * KS_STRIDE + c], &Qc[(size_t)row * 32 + c]);
        }
        cpa_commit();
    }
    prefetch_tile(Ks0, Vs0, Kc, Vtc, 0, tid);

    cpa_wait<1>();          // Q ready (tile 0 may still fly)
    __syncthreads();

    unsigned qa[4][4];      // A-frags: {reg0,reg1,reg2,reg3} per k16 chunk
    {
        const int r0 = warp * 16 + gid;
        #pragma unroll
        for (int kc = 0; kc < 4; ++kc) {
            uint2 lo = *(const uint2*)&Ks1[(r0    ) * KS_STRIDE + kc * 8 + 2 * tig];
            uint2 hi = *(const uint2*)&Ks1[(r0 + 8) * KS_STRIDE + kc * 8 + 2 * tig];
            qa[kc][0] = lo.x;  qa[kc][2] = lo.y;
            qa[kc][1] = hi.x;  qa[kc][3] = hi.y;
        }
    }
    __syncthreads();        // Q-frag reads done before Ks1 is reused

    float o[8][4];
    #pragma unroll
    for (int nt = 0; nt < 8; ++nt)
        #pragma unroll
        for (int j = 0; j < 4; ++j) o[nt][j] = 0.0f;
    float m0 = -1e30f, m1 = -1e30f, l0 = 0.0f, l1 = 0.0f;

    #pragma unroll 1
    for (int kt2 = 0; kt2 < NKT / 2; ++kt2) {
        const int ktB = 2 * kt2 + 1;

        // ---- step A: prefetch tile ktB into buf1; compute buf0 ----
        prefetch_tile(Ks1, Vs1, Kc, Vtc, ktB * BN, tid);
        cpa_wait<1>();       // tile 2*kt2 complete
        __syncthreads();
        compute_tile(Ks0, Vs0, qa, o, m0, m1, l0, l1, gid, tig);
        __syncthreads();     // buf0 consumers done before next prefetch into it

        // ---- step B: prefetch tile ktB+1 into buf0; compute buf1 ----
        if (kt2 < NKT / 2 - 1) {
            prefetch_tile(Ks0, Vs0, Kc, Vtc, (ktB + 1) * BN, tid);
            cpa_wait<1>();   // tile ktB complete
        } else {
            cpa_wait<0>();   // last tile: drain everything
        }
        __syncthreads();
        compute_tile(Ks1, Vs1, qa, o, m0, m1, l0, l1, gid, tig);
        __syncthreads();     // buf1 consumers done before next prefetch into it
    }

    // ---- epilogue ----
    const float inv0 = 1.0f / l0, inv1 = 1.0f / l1;
    const int r0 = qbase + warp * 16 + gid;
    const int r1 = r0 + 8;
    #pragma unroll
    for (int nt2 = 0; nt2 < 8; ++nt2) {
        float2 e0, e1;
        e0.x = o[nt2][0] * inv0; e0.y = o[nt2][1] * inv0;
        e1.x = o[nt2][2] * inv1; e1.y = o[nt2][3] * inv1;
        *(float2*)&O[base + (size_t)r0 * DH + nt2 * 8 + 2 * tig] = e0;
        *(float2*)&O[base + (size_t)r1 * DH + nt2 * 8 + 2 * tig] = e1;
    }
}

extern "C" void kernel_launch(void* const* d_in, const int* in_sizes, int n_in,
                              void* d_out, int out_size)
{
    const float* Q = (const float*)d_in[0];
    const float* K = (const float*)d_in[1];
    const float* V = (const float*)d_in[2];
    float* O = (float*)d_out;

    const float SC = 0.125f * 1.4426950408889634f;

    unsigned *dQh, *dKh, *dVh;
    cudaGetSymbolAddress((void**)&dQh, g_Qh);
    cudaGetSymbolAddress((void**)&dKh, g_Kh);
    cudaGetSymbolAddress((void**)&dVh, g_Vh);

    const int ng = TOT / 16;                 // 16-element groups
    cvt_h2_kernel<<<ng / 256, 256>>>(Q, dQh, SC);
    cvt_h2_kernel<<<ng / 256, 256>>>(K, dKh, 1.0f);

    dim3 tg(SEQ / 32, DH / 32, 64);
    transpose_vh_kernel<<<tg, dim3(32, 8)>>>(V, dVh);

    cudaFuncSetAttribute(attn_f16_kernel,
                         cudaFuncAttributeMaxDynamicSharedMemorySize, SMEM_BYTES);

    dim3 grid(SEQ / BM, 64);
    attn_f16_kernel<<<grid, NT, SMEM_BYTES>>>(O);
}

// round 17
// speedup vs baseline: 2.9019x; 1.2095x over previous
#include <cuda_runtime.h>
#include <cuda_fp16.h>

// Scaled dot-product attention, B=4 H=16 S=2048 D=64, fp32 in/out.
// R15: R14 fp16-MMA pipeline +
//  - fixed (de-duplicated) V-transpose prepass, fused Q/K cvt
//  - softmax exp via ex2.approx.f16x2 (produces GEMM2 A-frags directly)
//  - row-sum l computed by tensor core: extra MMA with constant B = 1.0h

#define DH 64
#define BM 128
#define BN 128
#define NT 256
#define SEQ 2048
#define NKT (SEQ / BN)     /* 16 */

#define KS_STRIDE 40       /* words/row (32 data) */
#define VT_STRIDE 72       /* words/row (64 data) */
#define KS_BYTES (BN * KS_STRIDE * 4)       /* 20480 */
#define VT_BYTES (DH * VT_STRIDE * 4)       /* 18432 */
#define BUF_BYTES (KS_BYTES + VT_BYTES)     /* 38912 */
#define SMEM_BYTES (2 * BUF_BYTES)          /* 77824 */

#define TOT (4 * 16 * 2048 * 64)            /* 8388608 elements per tensor */
#define ONESH2 0x3C003C00u                  /* {1.0h, 1.0h} */

__device__ unsigned g_Qh[TOT / 2];   // fp16 pairs, permuted-d, scaled
__device__ unsigned g_Kh[TOT / 2];   // fp16 pairs, permuted-d
__device__ unsigned g_Vh[TOT / 2];   // fp16 pairs, transposed [d][k], permuted-k

__device__ __forceinline__ unsigned packh2(float hi, float lo) {
    unsigned u;
    asm("cvt.rn.f16x2.f32 %0, %1, %2;" : "=r"(u) : "f"(hi), "f"(lo));
    return u;
}
__device__ __forceinline__ float ex2f(float x) {
    float r; asm("ex2.approx.f32 %0, %1;" : "=f"(r) : "f"(x)); return r;
}
__device__ __forceinline__ unsigned h2ex2(unsigned u) {
    unsigned r; asm("ex2.approx.f16x2 %0, %1;" : "=r"(r) : "r"(u)); return r;
}
__device__ __forceinline__ void mma_f16(float c[4],
                                        unsigned a0, unsigned a1,
                                        unsigned a2, unsigned a3,
                                        unsigned b0, unsigned b1) {
    asm("mma.sync.aligned.m16n8k16.row.col.f32.f16.f16.f32 "
        "{%0,%1,%2,%3}, {%4,%5,%6,%7}, {%8,%9}, {%0,%1,%2,%3};"
        : "+f"(c[0]), "+f"(c[1]), "+f"(c[2]), "+f"(c[3])
        : "r"(a0), "r"(a1), "r"(a2), "r"(a3), "r"(b0), "r"(b1));
}
__device__ __forceinline__ void cpa16(void* dst_smem, const void* src) {
    unsigned d = (unsigned)__cvta_generic_to_shared(dst_smem);
    asm volatile("cp.async.cg.shared.global [%0], [%1], 16;" :: "r"(d), "l"(src));
}
__device__ __forceinline__ void cpa_commit() {
    asm volatile("cp.async.commit_group;");
}
template <int N> __device__ __forceinline__ void cpa_wait() {
    asm volatile("cp.async.wait_group %0;" :: "n"(N));
}

// ---- prepass A: fp32 -> fp16 pairs, permute pair-words in each 16-elem group.
// grid.y = 0 -> Q (scaled), 1 -> K. slot s holds pair j = (s&1)*4 + (s>>1).
__global__ void __launch_bounds__(256) cvt_h2_qk_kernel(
    const float* __restrict__ Q, const float* __restrict__ K,
    unsigned* __restrict__ Qd, unsigned* __restrict__ Kd, float qscale)
{
    const float* src = blockIdx.y ? K : Q;
    unsigned* dst = blockIdx.y ? Kd : Qd;
    float scale = blockIdx.y ? 1.0f : qscale;
    int i = blockIdx.x * 256 + threadIdx.x;      // one 16-element group
    const float4* s = (const float4*)(src) + 4 * (size_t)i;
    float4 v0 = s[0], v1 = s[1], v2 = s[2], v3 = s[3];
    float f[16] = { v0.x, v0.y, v0.z, v0.w, v1.x, v1.y, v1.z, v1.w,
                    v2.x, v2.y, v2.z, v2.w, v3.x, v3.y, v3.z, v3.w };
    #pragma unroll
    for (int t = 0; t < 16; ++t) f[t] *= scale;
    uint4 oA, oB;
    oA.x = packh2(f[1],  f[0]);
    oA.y = packh2(f[9],  f[8]);
    oA.z = packh2(f[3],  f[2]);
    oA.w = packh2(f[11], f[10]);
    oB.x = packh2(f[5],  f[4]);
    oB.y = packh2(f[13], f[12]);
    oB.z = packh2(f[7],  f[6]);
    oB.w = packh2(f[15], f[14]);
    uint4* d = (uint4*)(dst) + 2 * (size_t)i;
    d[0] = oA;
    d[1] = oB;
}

// ---- prepass B: per-head transpose V[k][d] -> Vt[d][k], pair-permuted fp16.
// Block (32,8): tile 128k x 32d. Thread writes d-row txi, k-group tyi. ----
__global__ void __launch_bounds__(256) transpose_vh_kernel(
    const float* __restrict__ V, unsigned* __restrict__ Vt)
{
    __shared__ float t[128][33];
    const int k0 = blockIdx.x * 128;
    const int d0 = blockIdx.y * 32;
    const size_t hb = (size_t)blockIdx.z * (SEQ * DH);
    const int txi = threadIdx.x;   // 0..31
    const int tyi = threadIdx.y;   // 0..7

    #pragma unroll
    for (int j = 0; j < 16; ++j) {
        int kr = tyi + j * 8;
        t[kr][txi] = V[hb + (size_t)(k0 + kr) * DH + d0 + txi];
    }
    __syncthreads();

    const float* r = &t[tyi * 16][0];        // this thread's 16-k group
    uint4 oA, oB;
    oA.x = packh2(r[1 * 33 + txi],  r[0 * 33 + txi]);
    oA.y = packh2(r[9 * 33 + txi],  r[8 * 33 + txi]);
    oA.z = packh2(r[3 * 33 + txi],  r[2 * 33 + txi]);
    oA.w = packh2(r[11 * 33 + txi], r[10 * 33 + txi]);
    oB.x = packh2(r[5 * 33 + txi],  r[4 * 33 + txi]);
    oB.y = packh2(r[13 * 33 + txi], r[12 * 33 + txi]);
    oB.z = packh2(r[7 * 33 + txi],  r[6 * 33 + txi]);
    oB.w = packh2(r[15 * 33 + txi], r[14 * 33 + txi]);
    size_t wbase = (hb >> 1) + (size_t)(d0 + txi) * (SEQ / 2) + (k0 >> 1) + tyi * 8;
    *(uint4*)&Vt[wbase]     = oA;
    *(uint4*)&Vt[wbase + 4] = oB;
}

__device__ __forceinline__ void prefetch_tile(
    unsigned* __restrict__ Kn, unsigned* __restrict__ Vn,
    const unsigned* __restrict__ Kc, const unsigned* __restrict__ Vtc,
    int kb, int tid)
{
    #pragma unroll
    for (int it = 0; it < 4; ++it) {             // K: 128 rows x 32 words
        int idx = tid + it * NT;
        int row = idx >> 3;
        int c = (idx & 7) << 2;
        cpa16(&Kn[row * KS_STRIDE + c], &Kc[(size_t)(kb + row) * 32 + c]);
    }
    #pragma unroll
    for (int it = 0; it < 4; ++it) {             // Vt: 64 rows x 64 words
        int idx = tid + it * NT;
        int row = idx >> 4;
        int c = (idx & 15) << 2;
        cpa16(&Vn[row * VT_STRIDE + c], &Vtc[(size_t)row * (SEQ / 2) + (kb >> 1) + c]);
    }
    cpa_commit();
}

__device__ __forceinline__ void compute_tile(
    const unsigned* __restrict__ Kb, const unsigned* __restrict__ Vb,
    const unsigned (&qa)[4][4], float (&o)[8][4],
    float& m0, float& m1, float& l0, float& l1,
    int gid, int tig)
{
    // ---- GEMM1: S = Q @ K^T (16 n-tiles of 16x8, 4 k16 chunks) ----
    float c[16][4];
    #pragma unroll
    for (int nt = 0; nt < 16; ++nt)
        #pragma unroll
        for (int j = 0; j < 4; ++j) c[nt][j] = 0.0f;

    #pragma unroll
    for (int kc = 0; kc < 4; ++kc) {
        #pragma unroll
        for (int nt = 0; nt < 16; ++nt) {
            uint2 b = *(const uint2*)&Kb[(nt * 8 + gid) * KS_STRIDE + kc * 8 + 2 * tig];
            mma_f16(c[nt], qa[kc][0], qa[kc][1], qa[kc][2], qa[kc][3], b.x, b.y);
        }
    }

    // ---- online softmax (log2 domain); rows gid, gid+8 ----
    float mx0 = -1e30f, mx1 = -1e30f;
    #pragma unroll
    for (int nt = 0; nt < 16; ++nt) {
        mx0 = fmaxf(mx0, fmaxf(c[nt][0], c[nt][1]));
        mx1 = fmaxf(mx1, fmaxf(c[nt][2], c[nt][3]));
    }
    #pragma unroll
    for (int off = 1; off <= 2; off <<= 1) {
        mx0 = fmaxf(mx0, __shfl_xor_sync(0xffffffffu, mx0, off));
        mx1 = fmaxf(mx1, __shfl_xor_sync(0xffffffffu, mx1, off));
    }
    float mn0 = fmaxf(m0, mx0), mn1 = fmaxf(m1, mx1);
    float f0 = ex2f(m0 - mn0), f1 = ex2f(m1 - mn1);
    m0 = mn0; m1 = mn1;

    // exp in packed fp16: directly yields GEMM2 A-fragment words
    unsigned p01[16], p23[16];
    #pragma unroll
    for (int nt = 0; nt < 16; ++nt) {
        p01[nt] = h2ex2(packh2(c[nt][1] - mn0, c[nt][0] - mn0));
        p23[nt] = h2ex2(packh2(c[nt][3] - mn1, c[nt][2] - mn1));
    }

    #pragma unroll
    for (int nt = 0; nt < 8; ++nt) {
        o[nt][0] *= f0; o[nt][1] *= f0;
        o[nt][2] *= f1; o[nt][3] *= f1;
    }

    // ---- GEMM2: O += P @ V; row-sum l via extra MMA with B = ones ----
    float lacc[4] = { 0.0f, 0.0f, 0.0f, 0.0f };
    #pragma unroll
    for (int kc = 0; kc < 8; ++kc) {
        unsigned pa0 = p01[2 * kc];
        unsigned pa1 = p23[2 * kc];
        unsigned pa2 = p01[2 * kc + 1];
        unsigned pa3 = p23[2 * kc + 1];
        mma_f16(lacc, pa0, pa1, pa2, pa3, ONESH2, ONESH2);
        #pragma unroll
        for (int nt2 = 0; nt2 < 8; ++nt2) {
            uint2 b = *(const uint2*)&Vb[(nt2 * 8 + gid) * VT_STRIDE + kc * 8 + 2 * tig];
            mma_f16(o[nt2], pa0, pa1, pa2, pa3, b.x, b.y);
        }
    }
    l0 = l0 * f0 + lacc[0];
    l1 = l1 * f1 + lacc[2];
}

__global__ void __launch_bounds__(NT, 1) attn_f16_v2_kernel(float* __restrict__ O)
{
    extern __shared__ char smem[];
    unsigned* Ks0 = (unsigned*)smem;
    unsigned* Vs0 = (unsigned*)(smem + KS_BYTES);
    unsigned* Ks1 = (unsigned*)(smem + BUF_BYTES);
    unsigned* Vs1 = (unsigned*)(smem + BUF_BYTES + KS_BYTES);

    const int tid  = threadIdx.x;
    const int lane = tid & 31;
    const int warp = tid >> 5;
    const int gid  = lane >> 2;
    const int tig  = lane & 3;

    const size_t base = (size_t)blockIdx.y * ((size_t)SEQ * DH);
    const int qbase = blockIdx.x * BM;

    const unsigned* Kc  = g_Kh + (base >> 1);
    const unsigned* Vtc = g_Vh + (base >> 1);

    // ---- prologue: async-stage Q (into Ks1 region) then tile 0 into buf0 ----
    {
        const unsigned* Qc = g_Qh + (base >> 1) + (size_t)qbase * 32;
        #pragma unroll
        for (int it = 0; it < 4; ++it) {
            int idx = tid + it * NT;
            int row = idx >> 3;
            int c = (idx & 7) << 2;
            cpa16(&Ks1[row * KS_STRIDE + c], &Qc[(size_t)row * 32 + c]);
        }
        cpa_commit();
    }
    prefetch_tile(Ks0, Vs0, Kc, Vtc, 0, tid);

    cpa_wait<1>();          // Q ready (tile 0 may still fly)
    __syncthreads();

    unsigned qa[4][4];      // A-frags per k16 chunk
    {
        const int r0 = warp * 16 + gid;
        #pragma unroll
        for (int kc = 0; kc < 4; ++kc) {
            uint2 lo = *(const uint2*)&Ks1[(r0    ) * KS_STRIDE + kc * 8 + 2 * tig];
            uint2 hi = *(const uint2*)&Ks1[(r0 + 8) * KS_STRIDE + kc * 8 + 2 * tig];
            qa[kc][0] = lo.x;  qa[kc][2] = lo.y;
            qa[kc][1] = hi.x;  qa[kc][3] = hi.y;
        }
    }
    __syncthreads();        // Q-frag reads done before Ks1 is reused

    float o[8][4];
    #pragma unroll
    for (int nt = 0; nt < 8; ++nt)
        #pragma unroll
        for (int j = 0; j < 4; ++j) o[nt][j] = 0.0f;
    float m0 = -1e30f, m1 = -1e30f, l0 = 0.0f, l1 = 0.0f;

    #pragma unroll 1
    for (int kt2 = 0; kt2 < NKT / 2; ++kt2) {
        const int ktB = 2 * kt2 + 1;

        // ---- step A: prefetch tile ktB into buf1; compute buf0 ----
        prefetch_tile(Ks1, Vs1, Kc, Vtc, ktB * BN, tid);
        cpa_wait<1>();       // tile 2*kt2 complete
        __syncthreads();
        compute_tile(Ks0, Vs0, qa, o, m0, m1, l0, l1, gid, tig);
        __syncthreads();     // buf0 consumers done before next prefetch into it

        // ---- step B: prefetch tile ktB+1 into buf0; compute buf1 ----
        if (kt2 < NKT / 2 - 1) {
            prefetch_tile(Ks0, Vs0, Kc, Vtc, (ktB + 1) * BN, tid);
            cpa_wait<1>();   // tile ktB complete
        } else {
            cpa_wait<0>();   // last tile: drain everything
        }
        __syncthreads();
        compute_tile(Ks1, Vs1, qa, o, m0, m1, l0, l1, gid, tig);
        __syncthreads();     // buf1 consumers done before next prefetch into it
    }

    // ---- epilogue ----
    const float inv0 = 1.0f / l0, inv1 = 1.0f / l1;
    const int r0 = qbase + warp * 16 + gid;
    const int r1 = r0 + 8;
    #pragma unroll
    for (int nt2 = 0; nt2 < 8; ++nt2) {
        float2 e0, e1;
        e0.x = o[nt2][0] * inv0; e0.y = o[nt2][1] * inv0;
        e1.x = o[nt2][2] * inv1; e1.y = o[nt2][3] * inv1;
        *(float2*)&O[base + (size_t)r0 * DH + nt2 * 8 + 2 * tig] = e0;
        *(float2*)&O[base + (size_t)r1 * DH + nt2 * 8 + 2 * tig] = e1;
    }
}

extern "C" void kernel_launch(void* const* d_in, const int* in_sizes, int n_in,
                              void* d_out, int out_size)
{
    const float* Q = (const float*)d_in[0];
    const float* K = (const float*)d_in[1];
    const float* V = (const float*)d_in[2];
    float* O = (float*)d_out;

    const float SC = 0.125f * 1.4426950408889634f;

    unsigned *dQh, *dKh, *dVh;
    cudaGetSymbolAddress((void**)&dQh, g_Qh);
    cudaGetSymbolAddress((void**)&dKh, g_Kh);
    cudaGetSymbolAddress((void**)&dVh, g_Vh);

    const int ng = TOT / 16;                 // 16-element groups
    dim3 cg(ng / 256, 2);
    cvt_h2_qk_kernel<<<cg, 256>>>(Q, K, dQh, dKh, SC);

    dim3 tg(SEQ / 128, DH / 32, 64);
    transpose_vh_kernel<<<tg, dim3(32, 8)>>>(V, dVh);

    cudaFuncSetAttribute(attn_f16_v2_kernel,
                         cudaFuncAttributeMaxDynamicSharedMemorySize, SMEM_BYTES);

    dim3 grid(SEQ / BM, 64);
    attn_f16_v2_kernel<<<grid, NT, SMEM_BYTES>>>(O);
}